// round 1
// baseline (speedup 1.0000x reference)
#include <cuda_runtime.h>

// AdaptiveSample: out[b,c,h,w] = sum_s softmax_s(valid*posw*guide)[b,s,h,w] * feat_pad[b,c,h+dy_s-2,w+dx_s-2]
// plus passthrough copy of features as second tuple element.

namespace {
constexpr int H  = 256;
constexpr int W  = 512;
constexpr int C  = 32;
constexpr int B  = 2;
constexpr int S  = 15;
constexpr int KS = 5;
constexpr int KK = 25;

constexpr int BW = 32;  // block tile width  (== warp: coalesced w)
constexpr int BH = 8;   // block tile height
}

__global__ __launch_bounds__(BW * BH, 4)
void adaptive_sample_kernel(const float* __restrict__ depth,
                            const float* __restrict__ features,
                            const float* __restrict__ guide,
                            const int*   __restrict__ sidx,
                            float* __restrict__ out,
                            float* __restrict__ outf,
                            int do_copy)
{
    __shared__ float       sh_g[BH * BW * KK];  // guide tile, [ty][tx][k]
    __shared__ int         sh_off[S];
    __shared__ int         sh_idx[S];
    __shared__ float       sh_posw[S];
    __shared__ signed char sh_dy[S], sh_dx[S];

    const int tx  = threadIdx.x;
    const int ty  = threadIdx.y;
    const int tid = ty * BW + tx;
    const int w0  = blockIdx.x * BW;
    const int h0  = blockIdx.y * BH;
    const int b   = blockIdx.z;

    // --- one thread builds the per-sample metadata (S=15, trivial) ---
    if (tid == 0) {
        float pw[S];
        float sum = 0.f;
        #pragma unroll
        for (int s = 0; s < S; ++s) {
            int k  = sidx[s];
            int px = k % KS;
            int py = k / KS;
            float fx = (float)px - 2.f;
            float fy = (float)py - 2.f;
            float v  = __expf(-0.5f * sqrtf(fx * fx + fy * fy));
            pw[s] = v;
            sum  += v;
            sh_idx[s] = k;
            sh_dy[s]  = (signed char)(py - 2);
            sh_dx[s]  = (signed char)(px - 2);
            sh_off[s] = (py - 2) * W + (px - 2);
        }
        float inv = 1.f / sum;
        #pragma unroll
        for (int s = 0; s < S; ++s) sh_posw[s] = pw[s] * inv;
    }

    // --- stage guide tile into smem (float4 coalesced; row base is 3200B-aligned) ---
    #pragma unroll
    for (int r = 0; r < BH; ++r) {
        const float4* src = reinterpret_cast<const float4*>(
            guide + (((size_t)b * H + (h0 + r)) * W + w0) * KK);
        float4* dst = reinterpret_cast<float4*>(sh_g + r * BW * KK);
        for (int i = tid; i < BW * KK / 4; i += BW * BH)
            dst[i] = src[i];
    }
    __syncthreads();

    const int h = h0 + ty;
    const int w = w0 + tx;

    const float* drow = depth + (size_t)b * H * W;
    const float* gpix = sh_g + (ty * BW + tx) * KK;  // stride 25 across lanes: bank-conflict-free

    // --- per-pixel logits + softmax (shared by all 32 channels) ---
    float    wv[S];
    int      offs[S];
    unsigned ibm  = 0u;
    float    gmax = 0.f;   // logits are >= 0, so 0 is a safe lower bound
    #pragma unroll
    for (int s = 0; s < S; ++s) {
        int  hh = h + (int)sh_dy[s];
        int  ww = w + (int)sh_dx[s];
        bool ib = ((unsigned)hh < (unsigned)H) && ((unsigned)ww < (unsigned)W);
        float d = ib ? __ldg(drow + hh * W + ww) : 0.f;
        bool valid = ib && (d > 0.f) && (d < 192.0f);
        float logit = valid ? sh_posw[s] * gpix[sh_idx[s]] : 0.f;
        wv[s]  = logit;
        gmax   = fmaxf(gmax, logit);
        offs[s] = ib ? sh_off[s] : 0;   // clamp OOB to safe addr; weight zeroed below
        ibm    |= (unsigned)ib << s;
    }
    float esum = 0.f;
    #pragma unroll
    for (int s = 0; s < S; ++s) {
        wv[s] = __expf(wv[s] - gmax);
        esum += wv[s];
    }
    float inv = 1.f / esum;
    #pragma unroll
    for (int s = 0; s < S; ++s)
        wv[s] = ((ibm >> s) & 1u) ? wv[s] * inv : 0.f;  // OOB tap == padded zero feature

    // --- channel loop: 15 gathered FMAs per channel + passthrough copy ---
    const size_t pix  = (size_t)h * W + w;
    const size_t bimg = (size_t)b * C * H * W;
    const float* f    = features + bimg + pix;
    float*       o    = out  + bimg + pix;
    float*       oc   = outf + bimg + pix;
    constexpr int CS  = H * W;

    #pragma unroll 2
    for (int c = 0; c < C; ++c) {
        const float* fc = f + (size_t)c * CS;
        float acc = 0.f;
        #pragma unroll
        for (int s = 0; s < S; ++s)
            acc = fmaf(wv[s], __ldg(fc + offs[s]), acc);
        o[(size_t)c * CS] = acc;
        if (do_copy) oc[(size_t)c * CS] = __ldg(fc);
    }
}

extern "C" void kernel_launch(void* const* d_in, const int* in_sizes, int n_in,
                              void* d_out, int out_size)
{
    const float* depth    = (const float*)d_in[0];
    const float* features = (const float*)d_in[1];
    const float* guide    = (const float*)d_in[2];
    const int*   sidx     = (const int*)d_in[3];

    float* out = (float*)d_out;
    const int featN = in_sizes[1];                      // B*C*H*W
    const int do_copy = (out_size >= 2 * featN) ? 1 : 0; // tuple output: (out, features)
    float* outf = out + featN;

    dim3 block(BW, BH);
    dim3 grid(W / BW, H / BH, B);
    adaptive_sample_kernel<<<grid, block>>>(depth, features, guide, sidx,
                                            out, outf, do_copy);
}